// round 1
// baseline (speedup 1.0000x reference)
#include <cuda_runtime.h>
#include <math.h>

// Problem constants
#define T_STEPS 512
#define B_SZ    64
#define V_SZ    1024
#define HD      1024
#define G4      4096            // 4 * HD
#define NCTA    128             // persistent grid (<= 148 SMs, 1 CTA/SM -> co-resident)

// ---------------------------------------------------------------------------
// Scratch (static __device__ arrays: allowed; no runtime allocation)
// ---------------------------------------------------------------------------
__device__ float    g_XW[(size_t)T_STEPS * B_SZ * G4];   // 512 MB: x-projection of all gates
__device__ float    g_H[2][B_SZ * HD];                   // double-buffered recurrent state
__device__ unsigned g_bar_count;                         // grid barrier (self-resetting)
__device__ unsigned g_bar_gen;                           // monotonically increasing generation

// ---------------------------------------------------------------------------
// Init: copy H0 into g_H[0]   (runs every launch -> replay-safe)
// ---------------------------------------------------------------------------
__global__ void init_state_kernel(const float* __restrict__ H0) {
    int i = blockIdx.x * blockDim.x + threadIdx.x;   // grid covers B*HD/4 float4s
    ((float4*)g_H[0])[i] = ((const float4*)H0)[i];
}

// ---------------------------------------------------------------------------
// Phase 1: XW[m, g*HD + n] = sum_k inputs[m,k] * Wg[k,n]   (k < V)
//   M = T*B = 32768, N = 1024 per gate, K = 1024. fp32, SMEM tiled.
//   Tile: BM=128, BN=64, BK=16, 128 threads, 8x8 register tiles.
//   grid = (M/128, N/64, 4 gates)
// ---------------------------------------------------------------------------
__global__ __launch_bounds__(128)
void xw_gemm_kernel(const float* __restrict__ A,
                    const float* __restrict__ Wf, const float* __restrict__ Wi,
                    const float* __restrict__ Wc, const float* __restrict__ Wo)
{
    const int g = blockIdx.z;
    const float* __restrict__ W = (g == 0) ? Wf : (g == 1) ? Wi : (g == 2) ? Wc : Wo;

    __shared__ float As[16][128];   // [k][m]
    __shared__ float Bs[16][64];    // [k][n]

    const int m0  = blockIdx.x * 128;
    const int n0  = blockIdx.y * 64;
    const int tid = threadIdx.x;

    const int mr = (tid >> 3) * 8;  // 16 m-groups
    const int nc = (tid & 7) * 8;   // 8  n-groups

    float acc[8][8];
    #pragma unroll
    for (int i = 0; i < 8; i++)
        #pragma unroll
        for (int j = 0; j < 8; j++) acc[i][j] = 0.0f;

    for (int k0 = 0; k0 < V_SZ; k0 += 16) {
        // global loads into registers
        const float* Arow = A + (size_t)(m0 + tid) * V_SZ + k0;
        float4 a4[4];
        #pragma unroll
        for (int q = 0; q < 4; q++) a4[q] = *(const float4*)(Arow + 4 * q);

        float4 b4[2];
        #pragma unroll
        for (int p = 0; p < 2; p++) {
            int q  = tid + 128 * p;         // 256 float4s = 16x64 tile
            int r  = q >> 4;
            int cn = (q & 15) * 4;
            b4[p] = *(const float4*)(W + (size_t)(k0 + r) * HD + n0 + cn);
        }

        __syncthreads();   // previous tile's compute done before overwrite
        #pragma unroll
        for (int q = 0; q < 4; q++) {
            As[4 * q + 0][tid] = a4[q].x;
            As[4 * q + 1][tid] = a4[q].y;
            As[4 * q + 2][tid] = a4[q].z;
            As[4 * q + 3][tid] = a4[q].w;
        }
        #pragma unroll
        for (int p = 0; p < 2; p++) {
            int q  = tid + 128 * p;
            int r  = q >> 4;
            int cn = (q & 15) * 4;
            *(float4*)&Bs[r][cn] = b4[p];
        }
        __syncthreads();

        #pragma unroll
        for (int kk = 0; kk < 16; kk++) {
            float4 a0 = *(float4*)&As[kk][mr];
            float4 a1 = *(float4*)&As[kk][mr + 4];
            float4 w0 = *(float4*)&Bs[kk][nc];
            float4 w1 = *(float4*)&Bs[kk][nc + 4];
            float am[8] = {a0.x, a0.y, a0.z, a0.w, a1.x, a1.y, a1.z, a1.w};
            float wn[8] = {w0.x, w0.y, w0.z, w0.w, w1.x, w1.y, w1.z, w1.w};
            #pragma unroll
            for (int i = 0; i < 8; i++)
                #pragma unroll
                for (int j = 0; j < 8; j++)
                    acc[i][j] = fmaf(am[i], wn[j], acc[i][j]);
        }
    }

    // epilogue: strided store into the gate-concatenated layout [m][4096]
    #pragma unroll
    for (int i = 0; i < 8; i++) {
        float* Crow = g_XW + (size_t)(m0 + mr + i) * G4 + g * HD + n0 + nc;
        float4 v0 = make_float4(acc[i][0], acc[i][1], acc[i][2], acc[i][3]);
        float4 v1 = make_float4(acc[i][4], acc[i][5], acc[i][6], acc[i][7]);
        *(float4*)(Crow)     = v0;
        *(float4*)(Crow + 4) = v1;
    }
}

// ---------------------------------------------------------------------------
// Phase 2: persistent recurrent kernel.
//   128 CTAs x 128 threads. CTA cid owns hidden units h0 = cid*8 .. +7
//   (32 gate-columns). Its 1024x32 fp32 weight slice lives in SMEM for the
//   whole kernel. C-state lives in registers. Grid barrier per step.
// ---------------------------------------------------------------------------
__device__ __forceinline__ float sigmoidf_(float x) {
    return 1.0f / (1.0f + expf(-x));
}

// dynamic SMEM layout (floats):
//   Wsh : 1024*32 = 32768
//   Hs  : 16*64   = 1024
//   Gs  : 64*36   = 2304   (padded rows to avoid bank conflicts)
//   bsh : 32
#define SM_WSH 0
#define SM_HS  (1024 * 32)
#define SM_GS  (SM_HS + 16 * 64)
#define SM_BSH (SM_GS + 64 * 36)
#define SM_FLOATS (SM_BSH + 32)

__global__ __launch_bounds__(128, 1)
void lstm_recurrent_kernel(const float* __restrict__ C0,
                           const float* __restrict__ Wf, const float* __restrict__ Wi,
                           const float* __restrict__ Wc, const float* __restrict__ Wo,
                           const float* __restrict__ bf, const float* __restrict__ bi,
                           const float* __restrict__ bc, const float* __restrict__ bo,
                           float* __restrict__ out)
{
    extern __shared__ float sm[];
    float* Wsh = sm + SM_WSH;
    float* Hs  = sm + SM_HS;
    float* Gs  = sm + SM_GS;
    float* bsh = sm + SM_BSH;

    const int tid = threadIdx.x;        // 128
    const int cid = blockIdx.x;         // 128
    const int h0  = cid * 8;

    // ---- load this CTA's recurrent weight slice (rows V..V+HD-1) into SMEM
    {
        const float* Wptr[4] = {Wf, Wi, Wc, Wo};
        for (int idx = tid; idx < 1024 * 32; idx += 128) {
            int k = idx >> 5, c = idx & 31;
            int g = c >> 3,  jj = c & 7;
            Wsh[idx] = Wptr[g][(size_t)(V_SZ + k) * HD + h0 + jj];
        }
        if (tid < 32) {
            int g = tid >> 3, jj = tid & 7;
            const float* bp = (g == 0) ? bf : (g == 1) ? bi : (g == 2) ? bc : bo;
            bsh[tid] = bp[h0 + jj];
        }
    }

    // ---- per-thread roles
    // GEMM: 4 batches x 4 cols register tile
    const int mr4 = (tid >> 3) * 4;     // batch group 0..60
    const int nc4 = (tid & 7) * 4;      // col 0..28
    // elementwise: thread owns batch b, hidden hh0..hh0+3
    const int b   = tid >> 1;
    const int hh0 = (tid & 1) * 4;

    float cst[4];
    #pragma unroll
    for (int i = 0; i < 4; i++)
        cst[i] = C0[(size_t)b * HD + h0 + hh0 + i];

    __syncthreads();   // Wsh/bsh ready

    const unsigned nb = gridDim.x;

    for (int t = 0; t < T_STEPS; t++) {
        const float* Hcur = g_H[t & 1];

        float acc[4][4];
        #pragma unroll
        for (int i = 0; i < 4; i++)
            #pragma unroll
            for (int j = 0; j < 4; j++) acc[i][j] = 0.0f;

        for (int k0 = 0; k0 < HD; k0 += 16) {
            __syncthreads();   // previous Hs tile consumed
            {   // load H tile transposed: Hs[k][b]
                int bb = tid & 63;
                int kq = (tid >> 6) * 8;
                const float* hp = Hcur + (size_t)bb * HD + k0 + kq;
                float4 v0 = *(const float4*)(hp);
                float4 v1 = *(const float4*)(hp + 4);
                Hs[(kq + 0) * 64 + bb] = v0.x;
                Hs[(kq + 1) * 64 + bb] = v0.y;
                Hs[(kq + 2) * 64 + bb] = v0.z;
                Hs[(kq + 3) * 64 + bb] = v0.w;
                Hs[(kq + 4) * 64 + bb] = v1.x;
                Hs[(kq + 5) * 64 + bb] = v1.y;
                Hs[(kq + 6) * 64 + bb] = v1.z;
                Hs[(kq + 7) * 64 + bb] = v1.w;
            }
            __syncthreads();

            #pragma unroll
            for (int kk = 0; kk < 16; kk++) {
                float4 hv = *(float4*)&Hs[kk * 64 + mr4];
                float4 wv = *(float4*)&Wsh[(k0 + kk) * 32 + nc4];
                float hm[4] = {hv.x, hv.y, hv.z, hv.w};
                float wn[4] = {wv.x, wv.y, wv.z, wv.w};
                #pragma unroll
                for (int i = 0; i < 4; i++)
                    #pragma unroll
                    for (int j = 0; j < 4; j++)
                        acc[i][j] = fmaf(hm[i], wn[j], acc[i][j]);
            }
        }

        // stage pre-activations (recurrent part only) to SMEM, padded rows of 36
        #pragma unroll
        for (int i = 0; i < 4; i++)
            *(float4*)&Gs[(mr4 + i) * 36 + nc4] =
                make_float4(acc[i][0], acc[i][1], acc[i][2], acc[i][3]);
        __syncthreads();

        // ---- fused elementwise LSTM update for (b, h0+hh0 .. +3)
        const float* xw = g_XW + ((size_t)t * B_SZ + b) * G4 + h0 + hh0;
        float4 xf = *(const float4*)(xw);
        float4 xi = *(const float4*)(xw + HD);
        float4 xc = *(const float4*)(xw + 2 * HD);
        float4 xo = *(const float4*)(xw + 3 * HD);
        float xfa[4] = {xf.x, xf.y, xf.z, xf.w};
        float xia[4] = {xi.x, xi.y, xi.z, xi.w};
        float xca[4] = {xc.x, xc.y, xc.z, xc.w};
        float xoa[4] = {xo.x, xo.y, xo.z, xo.w};

        float hnew[4];
        #pragma unroll
        for (int i = 0; i < 4; i++) {
            int hh = hh0 + i;
            float fpre = Gs[b * 36 +      hh] + xfa[i] + bsh[hh];
            float ipre = Gs[b * 36 +  8 + hh] + xia[i] + bsh[8 + hh];
            float cpre = Gs[b * 36 + 16 + hh] + xca[i] + bsh[16 + hh];
            float opre = Gs[b * 36 + 24 + hh] + xoa[i] + bsh[24 + hh];
            float F  = sigmoidf_(fpre);
            float I  = sigmoidf_(ipre);
            float Ct = tanhf(cpre);
            float O  = sigmoidf_(opre);
            cst[i]  = cst[i] * F + I * Ct;
            hnew[i] = tanhf(cst[i]) * O;
        }
        float4 hv4 = make_float4(hnew[0], hnew[1], hnew[2], hnew[3]);

        // write H: next-step buffer + states output
        *(float4*)(g_H[(t + 1) & 1] + (size_t)b * HD + h0 + hh0) = hv4;
        *(float4*)(out + ((size_t)t * B_SZ + b) * HD + h0 + hh0) = hv4;

        if (t == T_STEPS - 1) {
            size_t S = (size_t)T_STEPS * B_SZ * HD;
            *(float4*)(out + S + (size_t)b * HD + h0 + hh0) = hv4;   // Hf
            float4 cv4 = make_float4(cst[0], cst[1], cst[2], cst[3]);
            *(float4*)(out + S + (size_t)B_SZ * HD + (size_t)b * HD + h0 + hh0) = cv4; // Cf
        }

        // ---- grid barrier (generation-counting; replay-safe) ----
        __syncthreads();
        if (tid == 0) {
            __threadfence();
            volatile unsigned* genp = &g_bar_gen;
            unsigned my_gen = *genp;
            unsigned old = atomicAdd(&g_bar_count, 1u);
            if (old == nb - 1) {
                atomicExch(&g_bar_count, 0u);
                __threadfence();
                atomicAdd(&g_bar_gen, 1u);
            } else {
                while (*genp == my_gen) { }
            }
            __threadfence();
        }
        __syncthreads();
    }
}

// ---------------------------------------------------------------------------
// Launch
// ---------------------------------------------------------------------------
extern "C" void kernel_launch(void* const* d_in, const int* in_sizes, int n_in,
                              void* d_out, int out_size)
{
    const float* inputs = (const float*)d_in[0];   // (T, B, V)
    const float* H0     = (const float*)d_in[1];   // (B, Hd)
    const float* C0     = (const float*)d_in[2];   // (B, Hd)
    const float* Wf     = (const float*)d_in[3];   // (V+Hd, Hd)
    const float* bf     = (const float*)d_in[4];
    const float* Wi     = (const float*)d_in[5];
    const float* bi     = (const float*)d_in[6];
    const float* Wc     = (const float*)d_in[7];
    const float* bc     = (const float*)d_in[8];
    const float* Wo     = (const float*)d_in[9];
    const float* bo     = (const float*)d_in[10];
    float* out = (float*)d_out;

    (void)in_sizes; (void)n_in; (void)out_size;

    // opt-in to >48KB dynamic SMEM for the persistent kernel (idempotent)
    cudaFuncSetAttribute(lstm_recurrent_kernel,
                         cudaFuncAttributeMaxDynamicSharedMemorySize,
                         SM_FLOATS * (int)sizeof(float));

    // init recurrent H buffer
    init_state_kernel<<<(B_SZ * HD / 4 + 255) / 256, 256>>>(H0);

    // phase 1: x-projection for all timesteps, all 4 gates
    {
        dim3 grid(T_STEPS * B_SZ / 128, HD / 64, 4);
        xw_gemm_kernel<<<grid, 128>>>(inputs, Wf, Wi, Wc, Wo);
    }

    // phase 2: persistent recurrence
    lstm_recurrent_kernel<<<NCTA, 128, SM_FLOATS * (int)sizeof(float)>>>(
        C0, Wf, Wi, Wc, Wo, bf, bi, bc, bo, out);
}

// round 4
// speedup vs baseline: 1.1734x; 1.1734x over previous
#include <cuda_runtime.h>
#include <cuda_bf16.h>
#include <math.h>
#include <stdint.h>

// ---------------------------------------------------------------------------
// Problem constants
// ---------------------------------------------------------------------------
#define T_STEPS 512
#define B_SZ    64
#define V_SZ    1024
#define HD      1024
#define G4      4096
#define M_TOT   (T_STEPS * B_SZ)     // 32768
#define NCTA    128

// ---------------------------------------------------------------------------
// Scratch (__device__ globals: no runtime allocation)
// ---------------------------------------------------------------------------
__device__ float         g_XW[(size_t)M_TOT * G4];      // 512 MB x-projection
__device__ __nv_bfloat16 g_Xhi[(size_t)M_TOT * V_SZ];   // 64 MB
__device__ __nv_bfloat16 g_Xlo[(size_t)M_TOT * V_SZ];   // 64 MB
__device__ __nv_bfloat16 g_Wthi[(size_t)G4 * V_SZ];     // 8 MB  Wt[n][k] = Wg[k][col]
__device__ __nv_bfloat16 g_Wtlo[(size_t)G4 * V_SZ];     // 8 MB
__device__ float         g_H[2][B_SZ * HD];
__device__ unsigned      g_bar_count;
__device__ unsigned      g_bar_gen;

// ---------------------------------------------------------------------------
// Helpers
// ---------------------------------------------------------------------------
__device__ __forceinline__ uint32_t smem_u32(const void* p) {
    uint32_t a;
    asm("{ .reg .u64 t; cvta.to.shared.u64 t, %1; cvt.u32.u64 %0, t; }" : "=r"(a) : "l"(p));
    return a;
}
#define CP_ASYNC16(dst, src) \
    asm volatile("cp.async.cg.shared.global [%0], [%1], 16;" :: "r"(dst), "l"(src) : "memory")
#define CP_COMMIT() asm volatile("cp.async.commit_group;" ::: "memory")
#define CP_WAIT1()  asm volatile("cp.async.wait_group 1;" ::: "memory")
#define CP_WAIT0()  asm volatile("cp.async.wait_group 0;" ::: "memory")

__device__ __forceinline__ void mma16816(float* c, const uint32_t* a, const uint32_t* b) {
    asm volatile("mma.sync.aligned.m16n8k16.row.col.f32.bf16.bf16.f32 "
                 "{%0,%1,%2,%3}, {%4,%5,%6,%7}, {%8,%9}, {%0,%1,%2,%3};"
                 : "+f"(c[0]), "+f"(c[1]), "+f"(c[2]), "+f"(c[3])
                 : "r"(a[0]), "r"(a[1]), "r"(a[2]), "r"(a[3]), "r"(b[0]), "r"(b[1]));
}

// ---------------------------------------------------------------------------
// Prep: split inputs X into bf16 hi/lo
// ---------------------------------------------------------------------------
__global__ void split_x_kernel(const float* __restrict__ X) {
    size_t i = ((size_t)blockIdx.x * blockDim.x + threadIdx.x) * 4;
    float4 v = *(const float4*)(X + i);
    float vv[4] = {v.x, v.y, v.z, v.w};
    __nv_bfloat16 hi[4], lo[4];
    #pragma unroll
    for (int j = 0; j < 4; j++) {
        hi[j] = __float2bfloat16(vv[j]);
        lo[j] = __float2bfloat16(vv[j] - __bfloat162float(hi[j]));
    }
    *(uint2*)(g_Xhi + i) = *(uint2*)hi;
    *(uint2*)(g_Xlo + i) = *(uint2*)lo;
}

// ---------------------------------------------------------------------------
// Prep: transpose+split W (first V rows) -> Wt[n = g*1024+col][k], bf16 hi/lo
// ---------------------------------------------------------------------------
__global__ void split_wt_kernel(const float* __restrict__ Wf, const float* __restrict__ Wi,
                                const float* __restrict__ Wc, const float* __restrict__ Wo) {
    const int g = blockIdx.z;
    const float* __restrict__ W = (g == 0) ? Wf : (g == 1) ? Wi : (g == 2) ? Wc : Wo;
    __shared__ float t[32][33];
    int k0 = blockIdx.x * 32, c0 = blockIdx.y * 32;
    t[threadIdx.y][threadIdx.x] = W[(size_t)(k0 + threadIdx.y) * HD + c0 + threadIdx.x];
    __syncthreads();
    float v = t[threadIdx.x][threadIdx.y];           // = W[k0+tx][c0+ty]
    size_t n = (size_t)g * HD + c0 + threadIdx.y;
    size_t k = k0 + threadIdx.x;
    __nv_bfloat16 hi = __float2bfloat16(v);
    __nv_bfloat16 lo = __float2bfloat16(v - __bfloat162float(hi));
    g_Wthi[n * V_SZ + k] = hi;
    g_Wtlo[n * V_SZ + k] = lo;
}

// ---------------------------------------------------------------------------
// Phase 1: bf16-split HMMA GEMM  g_XW[32768,4096] = X[.,1024] @ W[1024,4096]
//   CTA tile 128x128, BK=32, 256 threads = 8 warps (4m x 2n), warp tile 32x64.
//   mma.sync.m16n8k16 bf16->f32; 3-term split hi*hi + lo*hi + hi*lo.
//   cp.async double-buffered SMEM; row stride 40 elems (conflict-free).
// ---------------------------------------------------------------------------
#define P1_BM 128
#define P1_BN 128
#define P1_BK 32
#define P1_NCHUNK (V_SZ / P1_BK)     // 32
#define ROWSTRIDE 40                 // elements; 80B rows, 16B-aligned, CF banks

// SMEM byte offsets within one stage
#define OAHI 0
#define OALO 10240
#define OBHI 20480
#define OBLO 30720
#define STAGE_B 40960
#define P1_SMEM (2 * STAGE_B)        // 80 KB

__device__ __forceinline__ void issue_chunk(uint32_t stage_sa, int c,
                                            size_t m0, size_t n0, int tid) {
    // 512 uint4 per array; 256 threads x 2
    #pragma unroll
    for (int q = 0; q < 2; q++) {
        int idx = tid + 256 * q;
        int row = idx >> 2;          // 0..127
        int kq  = idx & 3;           // 0..3  (8 bf16 = 16B each)
        uint32_t dst = stage_sa + row * (ROWSTRIDE * 2) + kq * 16;
        size_t   se  = (m0 + row) * V_SZ + (size_t)c * P1_BK + kq * 8;
        CP_ASYNC16(dst + OAHI, g_Xhi + se);
        CP_ASYNC16(dst + OALO, g_Xlo + se);
        size_t   sw  = (n0 + row) * V_SZ + (size_t)c * P1_BK + kq * 8;
        CP_ASYNC16(dst + OBHI, g_Wthi + sw);
        CP_ASYNC16(dst + OBLO, g_Wtlo + sw);
    }
    CP_COMMIT();
}

__global__ __launch_bounds__(256, 1)
void xw_mma_kernel() {
    extern __shared__ char smem[];
    const uint32_t sb = smem_u32(smem);
    const int tid  = threadIdx.x;
    const int wid  = tid >> 5;
    const int lane = tid & 31;
    const int wm   = wid & 3;        // 4 m-warps, 32 rows each
    const int wn   = wid >> 2;       // 2 n-warps, 64 cols each

    const size_t m0 = (size_t)blockIdx.y * P1_BM;
    const size_t n0 = (size_t)blockIdx.x * P1_BN;

    float acc[2][8][4];
    #pragma unroll
    for (int i = 0; i < 2; i++)
        #pragma unroll
        for (int j = 0; j < 8; j++)
            #pragma unroll
            for (int r = 0; r < 4; r++) acc[i][j][r] = 0.0f;

    issue_chunk(sb, 0, m0, n0, tid);

    const int lr = lane >> 2;        // 0..7
    const int lc = (lane & 3) * 2;   // 0,2,4,6

    for (int c = 0; c < P1_NCHUNK; c++) {
        const uint32_t cur = sb + (c & 1) * STAGE_B;
        if (c + 1 < P1_NCHUNK) {
            issue_chunk(sb + ((c + 1) & 1) * STAGE_B, c + 1, m0, n0, tid);
            CP_WAIT1();
        } else {
            CP_WAIT0();
        }
        __syncthreads();

        const char* s = smem + (c & 1) * STAGE_B;
        #pragma unroll
        for (int ks = 0; ks < 2; ks++) {
            // ---- A fragments (2 m-frags x {hi,lo}), 4 b32 regs each
            uint32_t ah[2][4], al[2][4];
            #pragma unroll
            for (int fm = 0; fm < 2; fm++) {
                int r0 = wm * 32 + fm * 16 + lr;
                int cc = ks * 16 + lc;
                const char* base = s + (size_t)0;
                ah[fm][0] = *(const uint32_t*)(base + OAHI + (r0    ) * 80 + cc * 2);
                ah[fm][1] = *(const uint32_t*)(base + OAHI + (r0 + 8) * 80 + cc * 2);
                ah[fm][2] = *(const uint32_t*)(base + OAHI + (r0    ) * 80 + (cc + 8) * 2);
                ah[fm][3] = *(const uint32_t*)(base + OAHI + (r0 + 8) * 80 + (cc + 8) * 2);
                al[fm][0] = *(const uint32_t*)(base + OALO + (r0    ) * 80 + cc * 2);
                al[fm][1] = *(const uint32_t*)(base + OALO + (r0 + 8) * 80 + cc * 2);
                al[fm][2] = *(const uint32_t*)(base + OALO + (r0    ) * 80 + (cc + 8) * 2);
                al[fm][3] = *(const uint32_t*)(base + OALO + (r0 + 8) * 80 + (cc + 8) * 2);
            }
            // ---- B fragments (8 n-frags x {hi,lo}), 2 b32 regs each
            uint32_t bh[8][2], bl[8][2];
            #pragma unroll
            for (int fn = 0; fn < 8; fn++) {
                int nn = wn * 64 + fn * 8 + lr;
                int kk = ks * 16 + lc;
                bh[fn][0] = *(const uint32_t*)(s + OBHI + nn * 80 + kk * 2);
                bh[fn][1] = *(const uint32_t*)(s + OBHI + nn * 80 + (kk + 8) * 2);
                bl[fn][0] = *(const uint32_t*)(s + OBLO + nn * 80 + kk * 2);
                bl[fn][1] = *(const uint32_t*)(s + OBLO + nn * 80 + (kk + 8) * 2);
            }
            // ---- MMAs: hi*hi + lo*hi + hi*lo
            #pragma unroll
            for (int fm = 0; fm < 2; fm++)
                #pragma unroll
                for (int fn = 0; fn < 8; fn++) {
                    mma16816(acc[fm][fn], ah[fm], bh[fn]);
                    mma16816(acc[fm][fn], al[fm], bh[fn]);
                    mma16816(acc[fm][fn], ah[fm], bl[fn]);
                }
        }
        __syncthreads();
    }

    // ---- epilogue: write C tile to g_XW
    #pragma unroll
    for (int fm = 0; fm < 2; fm++) {
        #pragma unroll
        for (int fn = 0; fn < 8; fn++) {
            size_t row = m0 + wm * 32 + fm * 16 + lr;
            size_t col = n0 + wn * 64 + fn * 8 + lc;
            float2 v01 = make_float2(acc[fm][fn][0], acc[fm][fn][1]);
            float2 v23 = make_float2(acc[fm][fn][2], acc[fm][fn][3]);
            *(float2*)(g_XW + row * G4 + col)       = v01;
            *(float2*)(g_XW + (row + 8) * G4 + col) = v23;
        }
    }
}

// ---------------------------------------------------------------------------
// Init: copy H0 into g_H[0]
// ---------------------------------------------------------------------------
__global__ void init_state_kernel(const float* __restrict__ H0) {
    int i = blockIdx.x * blockDim.x + threadIdx.x;
    ((float4*)g_H[0])[i] = ((const float4*)H0)[i];
}

// ---------------------------------------------------------------------------
// Phase 2: persistent recurrent kernel (round-1-proven, unchanged)
// ---------------------------------------------------------------------------
__device__ __forceinline__ float sigmoidf_(float x) { return 1.0f / (1.0f + expf(-x)); }

#define SM_WSH 0
#define SM_HS  (1024 * 32)
#define SM_GS  (SM_HS + 16 * 64)
#define SM_BSH (SM_GS + 64 * 36)
#define SM_FLOATS (SM_BSH + 32)

__global__ __launch_bounds__(128, 1)
void lstm_recurrent_kernel(const float* __restrict__ C0,
                           const float* __restrict__ Wf, const float* __restrict__ Wi,
                           const float* __restrict__ Wc, const float* __restrict__ Wo,
                           const float* __restrict__ bf, const float* __restrict__ bi,
                           const float* __restrict__ bc, const float* __restrict__ bo,
                           float* __restrict__ out)
{
    extern __shared__ float sm[];
    float* Wsh = sm + SM_WSH;
    float* Hs  = sm + SM_HS;
    float* Gs  = sm + SM_GS;
    float* bsh = sm + SM_BSH;

    const int tid = threadIdx.x;
    const int cid = blockIdx.x;
    const int h0  = cid * 8;

    {
        const float* Wptr[4] = {Wf, Wi, Wc, Wo};
        for (int idx = tid; idx < 1024 * 32; idx += 128) {
            int k = idx >> 5, c = idx & 31;
            int g = c >> 3,  jj = c & 7;
            Wsh[idx] = Wptr[g][(size_t)(V_SZ + k) * HD + h0 + jj];
        }
        if (tid < 32) {
            int g = tid >> 3, jj = tid & 7;
            const float* bp = (g == 0) ? bf : (g == 1) ? bi : (g == 2) ? bc : bo;
            bsh[tid] = bp[h0 + jj];
        }
    }

    const int mr4 = (tid >> 3) * 4;
    const int nc4 = (tid & 7) * 4;
    const int b   = tid >> 1;
    const int hh0 = (tid & 1) * 4;

    float cst[4];
    #pragma unroll
    for (int i = 0; i < 4; i++)
        cst[i] = C0[(size_t)b * HD + h0 + hh0 + i];

    __syncthreads();

    const unsigned nb = gridDim.x;

    for (int t = 0; t < T_STEPS; t++) {
        const float* Hcur = g_H[t & 1];

        float acc[4][4];
        #pragma unroll
        for (int i = 0; i < 4; i++)
            #pragma unroll
            for (int j = 0; j < 4; j++) acc[i][j] = 0.0f;

        for (int k0 = 0; k0 < HD; k0 += 16) {
            __syncthreads();
            {
                int bb = tid & 63;
                int kq = (tid >> 6) * 8;
                const float* hp = Hcur + (size_t)bb * HD + k0 + kq;
                float4 v0 = *(const float4*)(hp);
                float4 v1 = *(const float4*)(hp + 4);
                Hs[(kq + 0) * 64 + bb] = v0.x;
                Hs[(kq + 1) * 64 + bb] = v0.y;
                Hs[(kq + 2) * 64 + bb] = v0.z;
                Hs[(kq + 3) * 64 + bb] = v0.w;
                Hs[(kq + 4) * 64 + bb] = v1.x;
                Hs[(kq + 5) * 64 + bb] = v1.y;
                Hs[(kq + 6) * 64 + bb] = v1.z;
                Hs[(kq + 7) * 64 + bb] = v1.w;
            }
            __syncthreads();

            #pragma unroll
            for (int kk = 0; kk < 16; kk++) {
                float4 hv = *(float4*)&Hs[kk * 64 + mr4];
                float4 wv = *(float4*)&Wsh[(k0 + kk) * 32 + nc4];
                float hm[4] = {hv.x, hv.y, hv.z, hv.w};
                float wn[4] = {wv.x, wv.y, wv.z, wv.w};
                #pragma unroll
                for (int i = 0; i < 4; i++)
                    #pragma unroll
                    for (int j = 0; j < 4; j++)
                        acc[i][j] = fmaf(hm[i], wn[j], acc[i][j]);
            }
        }

        #pragma unroll
        for (int i = 0; i < 4; i++)
            *(float4*)&Gs[(mr4 + i) * 36 + nc4] =
                make_float4(acc[i][0], acc[i][1], acc[i][2], acc[i][3]);
        __syncthreads();

        const float* xw = g_XW + ((size_t)t * B_SZ + b) * G4 + h0 + hh0;
        float4 xf = *(const float4*)(xw);
        float4 xi = *(const float4*)(xw + HD);
        float4 xc = *(const float4*)(xw + 2 * HD);
        float4 xo = *(const float4*)(xw + 3 * HD);
        float xfa[4] = {xf.x, xf.y, xf.z, xf.w};
        float xia[4] = {xi.x, xi.y, xi.z, xi.w};
        float xca[4] = {xc.x, xc.y, xc.z, xc.w};
        float xoa[4] = {xo.x, xo.y, xo.z, xo.w};

        float hnew[4];
        #pragma unroll
        for (int i = 0; i < 4; i++) {
            int hh = hh0 + i;
            float fpre = Gs[b * 36 +      hh] + xfa[i] + bsh[hh];
            float ipre = Gs[b * 36 +  8 + hh] + xia[i] + bsh[8 + hh];
            float cpre = Gs[b * 36 + 16 + hh] + xca[i] + bsh[16 + hh];
            float opre = Gs[b * 36 + 24 + hh] + xoa[i] + bsh[24 + hh];
            float F  = sigmoidf_(fpre);
            float I  = sigmoidf_(ipre);
            float Ct = tanhf(cpre);
            float O  = sigmoidf_(opre);
            cst[i]  = cst[i] * F + I * Ct;
            hnew[i] = tanhf(cst[i]) * O;
        }
        float4 hv4 = make_float4(hnew[0], hnew[1], hnew[2], hnew[3]);

        *(float4*)(g_H[(t + 1) & 1] + (size_t)b * HD + h0 + hh0) = hv4;
        *(float4*)(out + ((size_t)t * B_SZ + b) * HD + h0 + hh0) = hv4;

        if (t == T_STEPS - 1) {
            size_t S = (size_t)T_STEPS * B_SZ * HD;
            *(float4*)(out + S + (size_t)b * HD + h0 + hh0) = hv4;
            float4 cv4 = make_float4(cst[0], cst[1], cst[2], cst[3]);
            *(float4*)(out + S + (size_t)B_SZ * HD + (size_t)b * HD + h0 + hh0) = cv4;
        }

        __syncthreads();
        if (tid == 0) {
            __threadfence();
            volatile unsigned* genp = &g_bar_gen;
            unsigned my_gen = *genp;
            unsigned old = atomicAdd(&g_bar_count, 1u);
            if (old == nb - 1) {
                atomicExch(&g_bar_count, 0u);
                __threadfence();
                atomicAdd(&g_bar_gen, 1u);
            } else {
                while (*genp == my_gen) { }
            }
            __threadfence();
        }
        __syncthreads();
    }
}

// ---------------------------------------------------------------------------
// Launch
// ---------------------------------------------------------------------------
extern "C" void kernel_launch(void* const* d_in, const int* in_sizes, int n_in,
                              void* d_out, int out_size)
{
    const float* inputs = (const float*)d_in[0];
    const float* H0     = (const float*)d_in[1];
    const float* C0     = (const float*)d_in[2];
    const float* Wf     = (const float*)d_in[3];
    const float* bf     = (const float*)d_in[4];
    const float* Wi     = (const float*)d_in[5];
    const float* bi     = (const float*)d_in[6];
    const float* Wc     = (const float*)d_in[7];
    const float* bc     = (const float*)d_in[8];
    const float* Wo     = (const float*)d_in[9];
    const float* bo     = (const float*)d_in[10];
    float* out = (float*)d_out;

    (void)in_sizes; (void)n_in; (void)out_size;

    cudaFuncSetAttribute(lstm_recurrent_kernel,
                         cudaFuncAttributeMaxDynamicSharedMemorySize,
                         SM_FLOATS * (int)sizeof(float));
    cudaFuncSetAttribute(xw_mma_kernel,
                         cudaFuncAttributeMaxDynamicSharedMemorySize, P1_SMEM);

    // init recurrent H buffer
    init_state_kernel<<<(B_SZ * HD / 4 + 255) / 256, 256>>>(H0);

    // prep: bf16 splits
    split_x_kernel<<<(int)(((size_t)M_TOT * V_SZ / 4) / 256), 256>>>(inputs);
    {
        dim3 grid(V_SZ / 32, HD / 32, 4);
        dim3 blk(32, 32);
        split_wt_kernel<<<grid, blk>>>(Wf, Wi, Wc, Wo);
    }

    // phase 1: HMMA x-projection  (grid: 32 N-tiles x 256 M-tiles)
    {
        dim3 grid(G4 / P1_BN, M_TOT / P1_BM);
        xw_mma_kernel<<<grid, 256, P1_SMEM>>>();
    }

    // phase 2: persistent recurrence
    lstm_recurrent_kernel<<<NCTA, 128, SM_FLOATS * (int)sizeof(float)>>>(
        C0, Wf, Wi, Wc, Wo, bf, bi, bc, bo, out);
}